// round 15
// baseline (speedup 1.0000x reference)
#include <cuda_runtime.h>
#include <cuda_fp16.h>
#include <cstdint>

typedef unsigned long long u64;
typedef unsigned int u32;
typedef unsigned short u16;

#define D_MODEL 1024
#define S_LEN   2048
#define NBATCH  4
#define NH      16
#define DKH     64
#define M_TOT   (NBATCH * S_LEN)   /* 8192 */
#define K_TOT   2048               /* concat of Xs|Xt feature dims */

// Scratch (no allocs).
__device__ u16 g_Ah[(size_t)M_TOT * K_TOT];            // [Xs|Xt], fp16
__device__ u16 g_Wh[3][(size_t)D_MODEL * K_TOT];       // [W_zs|W_zt], fp16
__device__ u16 g_Qh[(size_t)M_TOT * D_MODEL];          // Q bf16 hi
__device__ u16 g_Ql[(size_t)M_TOT * D_MODEL];          // Q bf16 lo
__device__ u16 g_Kh[(size_t)M_TOT * D_MODEL];          // K bf16 hi
__device__ u16 g_Kl[(size_t)M_TOT * D_MODEL];          // K bf16 lo
__device__ u16 g_Vh[(size_t)M_TOT * D_MODEL];          // V fp16

// ---------------- baseline (sm_80+) primitives ----------------
__device__ __forceinline__ u32 smem_u32(const void* p) {
    u32 a; asm("{ .reg .u64 t; cvta.to.shared.u64 t, %1; cvt.u32.u64 %0, t; }"
               : "=r"(a) : "l"(p));
    return a;
}
__device__ __forceinline__ void cp16(u32 dst, const void* src) {
    asm volatile("cp.async.cg.shared.global [%0], [%1], 16;" :: "r"(dst), "l"(src));
}
__device__ __forceinline__ void cp_commit() {
    asm volatile("cp.async.commit_group;" ::: "memory");
}
template <int N> __device__ __forceinline__ void cp_wait() {
    asm volatile("cp.async.wait_group %0;" :: "n"(N) : "memory");
}
// bf16: D = A(16x16,row) * B(16x8,col) + D
__device__ __forceinline__ void mma_bf16(float* c, const u32* a, u32 b0, u32 b1) {
    asm volatile(
        "mma.sync.aligned.m16n8k16.row.col.f32.bf16.bf16.f32 "
        "{%0,%1,%2,%3},{%4,%5,%6,%7},{%8,%9},{%0,%1,%2,%3};"
        : "+f"(c[0]), "+f"(c[1]), "+f"(c[2]), "+f"(c[3])
        : "r"(a[0]), "r"(a[1]), "r"(a[2]), "r"(a[3]), "r"(b0), "r"(b1));
}
// f16: D = A(16x16,row) * B(16x8,col) + D
__device__ __forceinline__ void mma_f16(float* c, const u32* a, u32 b0, u32 b1) {
    asm volatile(
        "mma.sync.aligned.m16n8k16.row.col.f32.f16.f16.f32 "
        "{%0,%1,%2,%3},{%4,%5,%6,%7},{%8,%9},{%0,%1,%2,%3};"
        : "+f"(c[0]), "+f"(c[1]), "+f"(c[2]), "+f"(c[3])
        : "r"(a[0]), "r"(a[1]), "r"(a[2]), "r"(a[3]), "r"(b0), "r"(b1));
}
#define LDSM4(r0, r1, r2, r3, a)                                             \
    asm volatile("ldmatrix.sync.aligned.m8n8.x4.shared.b16 {%0,%1,%2,%3},[%4];" \
        : "=r"(r0), "=r"(r1), "=r"(r2), "=r"(r3) : "r"(a))
#define LDSM4T(r0, r1, r2, r3, a)                                            \
    asm volatile("ldmatrix.sync.aligned.m8n8.x4.trans.shared.b16 {%0,%1,%2,%3},[%4];" \
        : "=r"(r0), "=r"(r1), "=r"(r2), "=r"(r3) : "r"(a))

// bf16 pack/unpack (hi goes to upper 16 bits)
__device__ __forceinline__ u32 bf16x2(float hi, float lo) {
    u32 d; asm("cvt.rn.bf16x2.f32 %0,%1,%2;" : "=r"(d) : "f"(hi), "f"(lo)); return d;
}
__device__ __forceinline__ float bflo(u32 x) { return __uint_as_float(x << 16); }
__device__ __forceinline__ float bfhi(u32 x) { return __uint_as_float(x & 0xffff0000u); }
// f16 pack (lo in low half, hi in high half), rne = unbiased
__device__ __forceinline__ u32 f16x2(float hi, float lo) {
    __half2 h = __floats2half2_rn(lo, hi);
    return *(u32*)&h;
}

// =========================================================================
// Pre-convert: fp16 A = [Xs|Xt] and W_z = [W_zs|W_zt].
// =========================================================================
__global__ __launch_bounds__(256) void conv_A_kernel(
    const float* __restrict__ Xs, const float* __restrict__ Xt)
{
    int idx = blockIdx.x * 256 + threadIdx.x;      // over 8192*256 chunks of 8
    if (idx >= M_TOT * (K_TOT / 8)) return;
    int row = idx >> 8, c8 = idx & 255;
    int col = c8 * 8;
    const float* src = (col < 1024) ? &Xs[(size_t)row * 1024 + col]
                                    : &Xt[(size_t)row * 1024 + col - 1024];
    float4 v0 = ((const float4*)src)[0];
    float4 v1 = ((const float4*)src)[1];
    uint4 o;
    o.x = f16x2(v0.y, v0.x); o.y = f16x2(v0.w, v0.z);
    o.z = f16x2(v1.y, v1.x); o.w = f16x2(v1.w, v1.z);
    *(uint4*)&g_Ah[(size_t)row * K_TOT + col] = o;
}

__global__ __launch_bounds__(256) void conv_W_kernel(
    const float* __restrict__ Wqs, const float* __restrict__ Wqt,
    const float* __restrict__ Wks, const float* __restrict__ Wkt,
    const float* __restrict__ Wvs, const float* __restrict__ Wvt)
{
    int z = blockIdx.z;
    const float *Wa, *Wb;
    if (z == 0)      { Wa = Wqs; Wb = Wqt; }
    else if (z == 1) { Wa = Wks; Wb = Wkt; }
    else             { Wa = Wvs; Wb = Wvt; }
    int idx = blockIdx.x * 256 + threadIdx.x;      // over 1024*256 chunks of 8
    if (idx >= D_MODEL * (K_TOT / 8)) return;
    int row = idx >> 8, c8 = idx & 255;
    int col = c8 * 8;
    const float* src = (col < 1024) ? &Wa[(size_t)row * 1024 + col]
                                    : &Wb[(size_t)row * 1024 + col - 1024];
    float4 v0 = ((const float4*)src)[0];
    float4 v1 = ((const float4*)src)[1];
    uint4 o;
    o.x = f16x2(v0.y, v0.x); o.y = f16x2(v0.w, v0.z);
    o.z = f16x2(v1.y, v1.x); o.w = f16x2(v1.w, v1.z);
    *(uint4*)&g_Wh[z][(size_t)row * K_TOT + col] = o;
}

// =========================================================================
// Projection GEMM via mma.sync f16 (fp32 accum), fused split epilogue.
// (unchanged R14 — passing, near its floor)
// =========================================================================
#define PJ_KC     64
#define PJ_NK     (K_TOT / PJ_KC)    /* 32 */
#define PRS       72                 /* u16 row stride (144B) */
#define PSTG_A    (128 * PRS * 2)    /* 18432 B */
#define PSTG_B    (256 * PRS * 2)    /* 36864 B */
#define PSTG      (PSTG_A + PSTG_B)  /* 55296 B */
#define PN_STG    4
#define PSM_BIAS  (PN_STG * PSTG)    /* 221184 */
#define PSM_TOTAL (PSM_BIAS + 1024 + 64)

__global__ void __launch_bounds__(256, 1) proj_mma_kernel(
    const float* __restrict__ bqs, const float* __restrict__ bqt,
    const float* __restrict__ bks, const float* __restrict__ bkt,
    const float* __restrict__ bvs, const float* __restrict__ bvt)
{
    extern __shared__ char sm[];
    const u32 smb = smem_u32(sm);
    const int t    = threadIdx.x;
    const int wid  = t >> 5;
    const int lane = t & 31;
    const int g    = lane >> 2;
    const int c    = lane & 3;
    const int wm   = (wid >> 2) * 64;
    const int wn   = (wid & 3) * 64;
    const int m0   = blockIdx.x * 128;
    const int n0   = blockIdx.y * 256;
    const int z    = blockIdx.z;

    const float* bA; const float* bB;
    if (z == 0)      { bA = bqs; bB = bqt; }
    else if (z == 1) { bA = bks; bB = bkt; }
    else             { bA = bvs; bB = bvt; }

    const u16* gAp = g_Ah;
    const u16* gWp = g_Wh[z];

    if (t < 64) {
        float4 a = *(const float4*)&bA[n0 + t * 4];
        float4 b = *(const float4*)&bB[n0 + t * 4];
        *(float4*)(sm + PSM_BIAS + t * 16) =
            make_float4(a.x + b.x, a.y + b.y, a.z + b.z, a.w + b.w);
    }

    float acc[4][8][4];
    #pragma unroll
    for (int mt = 0; mt < 4; ++mt)
        #pragma unroll
        for (int nt = 0; nt < 8; ++nt)
            #pragma unroll
            for (int j = 0; j < 4; ++j) acc[mt][nt][j] = 0.f;

    auto issue = [&](int i) {
        const int s  = i % PN_STG;
        const int kc = i * PJ_KC;
        const u32 abase = smb + s * PSTG;
        const u32 bbase = abase + PSTG_A;
        #pragma unroll
        for (int j = 0; j < 4; ++j) {              // A: 1024 x 16B
            int sid = t + j * 256;
            int row = sid >> 3, seg = sid & 7;
            cp16(abase + row * (PRS * 2) + seg * 16,
                 &gAp[(size_t)(m0 + row) * K_TOT + kc + seg * 8]);
        }
        #pragma unroll
        for (int j = 0; j < 8; ++j) {              // B: 2048 x 16B
            int sid = t + j * 256;
            int row = sid >> 3, seg = sid & 7;
            cp16(bbase + row * (PRS * 2) + seg * 16,
                 &gWp[(size_t)(n0 + row) * K_TOT + kc + seg * 8]);
        }
        cp_commit();
    };

    issue(0);
    issue(1);

    #pragma unroll 1
    for (int i = 0; i < PJ_NK; ++i) {
        if (i + 2 < PJ_NK)      { issue(i + 2); cp_wait<2>(); }
        else if (i + 1 < PJ_NK) { cp_wait<1>(); }
        else                    { cp_wait<0>(); }
        __syncthreads();    // single barrier (4-stage, distance-2 proof: R14)

        const int s = i % PN_STG;
        const u32 As = smb + s * PSTG;
        const u32 Bs = As + PSTG_A;

        #pragma unroll
        for (int ks = 0; ks < 4; ++ks) {
            u32 a[4][4], b[4][4];
            #pragma unroll
            for (int mt = 0; mt < 4; ++mt) {
                int row = wm + mt * 16 + (lane & 15);
                int col = ks * 16 + ((lane >> 4) << 3);
                LDSM4(a[mt][0], a[mt][1], a[mt][2], a[mt][3],
                      As + (row * PRS + col) * 2);
            }
            #pragma unroll
            for (int np = 0; np < 4; ++np) {
                int row = wn + np * 16 + (lane & 7) + ((lane >> 4) << 3);
                int col = ks * 16 + (((lane >> 3) & 1) << 3);
                LDSM4(b[np][0], b[np][1], b[np][2], b[np][3],
                      Bs + (row * PRS + col) * 2);
            }
            #pragma unroll
            for (int mt = 0; mt < 4; ++mt)
                #pragma unroll
                for (int np = 0; np < 4; ++np) {
                    mma_f16(acc[mt][2*np],   a[mt], b[np][0], b[np][1]);
                    mma_f16(acc[mt][2*np+1], a[mt], b[np][2], b[np][3]);
                }
        }
    }

    // ---- fused epilogue: +bias, split-convert, store 16-bit ----
    const float* bias = (const float*)(sm + PSM_BIAS);
    #pragma unroll
    for (int mt = 0; mt < 4; ++mt) {
        #pragma unroll
        for (int nt = 0; nt < 8; ++nt) {
            int cc = wn + nt * 8 + 2 * c;
            int r0 = m0 + wm + mt * 16 + g;
            float b0 = bias[cc], b1 = bias[cc + 1];
            float x0 = acc[mt][nt][0] + b0, x1 = acc[mt][nt][1] + b1;
            float y0 = acc[mt][nt][2] + b0, y1 = acc[mt][nt][3] + b1;
            size_t o0 = (size_t)r0 * D_MODEL + n0 + cc;
            size_t o1 = (size_t)(r0 + 8) * D_MODEL + n0 + cc;
            if (z == 2) {
                *(u32*)&g_Vh[o0] = f16x2(x1, x0);
                *(u32*)&g_Vh[o1] = f16x2(y1, y0);
            } else {
                u32 h0 = bf16x2(x1, x0);
                u32 h1 = bf16x2(y1, y0);
                u32 l0 = bf16x2(x1 - bfhi(h0), x0 - bflo(h0));
                u32 l1 = bf16x2(y1 - bfhi(h1), y0 - bflo(h1));
                u16* dh = (z == 0) ? g_Qh : g_Kh;
                u16* dl = (z == 0) ? g_Ql : g_Kl;
                *(u32*)&dh[o0] = h0;  *(u32*)&dh[o1] = h1;
                *(u32*)&dl[o0] = l0;  *(u32*)&dl[o1] = l1;
            }
        }
    }
}

// =========================================================================
// Flash attention on tensor cores.  R15: 128-thread CTAs (4 warps, 64
// q-rows), 2 CTAs/SM — cross-CTA overlap hides softmax/barrier idle.
// QK bf16x3, PV fp16.  2-stage cp.async, two syncs/tile (sibling CTA
// absorbs barrier idle).  Per-warp math identical to R14 (bit-identical).
// =========================================================================
#define RS       72                    /* u16 row stride (144B) */
#define TILE_B   (128 * RS * 2)        /* 18432 B (K/V tile: 128 rows) */
#define QTILE_B  (64 * RS * 2)         /* 9216 B  (Q tile: 64 rows) */
#define STG3     (3 * TILE_B)          /* Kh+Kl+Vh = 55296 B */
#define AT_NSTG  2
#define ATT_SMEM (AT_NSTG * STG3)      /* 110592 B -> 2 CTAs/SM */
#define NT       (S_LEN / 128)         /* 16 */

__global__ void __launch_bounds__(128, 2) attn_mma_kernel(
    float* __restrict__ out, const float* __restrict__ biasp)
{
    extern __shared__ char smc[];
    const u32 smb = smem_u32(smc);

    const int t = threadIdx.x, w = t >> 5, lane = t & 31;
    const int g = lane >> 2, c2 = lane & 3;
    const int q0 = blockIdx.x * 64;
    const int bh = blockIdx.y, b = bh >> 4, h = bh & 15;
    const size_t base  = (size_t)b * S_LEN * D_MODEL + (size_t)h * DKH;
    const size_t rowb  = (size_t)b * S_LEN;
    const int    colb  = h * DKH;
    const float bias = biasp[0];
    const float NEGINF = __int_as_float(0xff800000);

    // cp.async pre-split K/V tile i -> stage i&1 (24 cp16/thread)
    auto stage_issue = [&](int i) {
        const u32 sb = smb + (i & 1) * STG3;
        const size_t r0 = (rowb + (size_t)i * 128) * D_MODEL + colb;
        #pragma unroll
        for (int j = 0; j < 8; ++j) {
            int sid = t + j * 128;            // 0..1023
            int row = sid >> 3, seg = sid & 7;
            size_t src = r0 + (size_t)row * D_MODEL + seg * 8;
            u32 dst = sb + row * (RS * 2) + seg * 16;
            cp16(dst,              &g_Kh[src]);
            cp16(dst + TILE_B,     &g_Kl[src]);
            cp16(dst + 2 * TILE_B, &g_Vh[src]);
        }
        cp_commit();
    };

    stage_issue(0);

    // Q (pre-split, 64 rows) staged through stage-1 area.
    {
        const u32 sb = smb + STG3;
        const size_t r0 = (rowb + (size_t)q0) * D_MODEL + colb;
        #pragma unroll
        for (int j = 0; j < 4; ++j) {
            int sid = t + j * 128;            // 0..511
            int row = sid >> 3, seg = sid & 7;
            size_t src = r0 + (size_t)row * D_MODEL + seg * 8;
            u32 dst = sb + row * (RS * 2) + seg * 16;
            cp16(dst,           &g_Qh[src]);
            cp16(dst + QTILE_B, &g_Ql[src]);
        }
        cp_commit();
    }
    cp_wait<0>();
    __syncthreads();

    u32 qh[4][4], ql[4][4];
    {
        int row = w * 16 + (lane & 15);       // w in [0,4): 64 q-rows
        int cb  = (lane >> 4) << 3;
        #pragma unroll
        for (int ks = 0; ks < 4; ++ks) {
            u32 ah = smb + STG3 + (row * RS + ks * 16 + cb) * 2;
            LDSM4(qh[ks][0], qh[ks][1], qh[ks][2], qh[ks][3], ah);
            LDSM4(ql[ks][0], ql[ks][1], ql[ks][2], ql[ks][3], ah + QTILE_B);
        }
    }
    __syncthreads();   // Q reads done before issue(1) overwrites stage 1

    float m0r = NEGINF, m1r = NEGINF, l0r = 0.f, l1r = 0.f;
    float O[8][4];
    #pragma unroll
    for (int nt = 0; nt < 8; ++nt)
        #pragma unroll
        for (int j = 0; j < 4; ++j) O[nt][j] = 0.f;

    #pragma unroll 1
    for (int kb = 0; kb < NT; ++kb) {
        if (kb + 1 < NT) { stage_issue(kb + 1); cp_wait<1>(); }
        else             { cp_wait<0>(); }
        __syncthreads();   // stage kb&1 data ready for all warps

        const u32 sb  = smb + (kb & 1) * STG3;
        const u32 khb = sb, klb = sb + TILE_B, vhb = sb + 2 * TILE_B;

        // ---- S = Q K^T : bf16x3 ----
        float S[16][4];
        #pragma unroll
        for (int nt = 0; nt < 16; ++nt)
            #pragma unroll
            for (int j = 0; j < 4; ++j) S[nt][j] = 0.f;

        #pragma unroll
        for (int ks = 0; ks < 4; ++ks) {
            #pragma unroll
            for (int ntp = 0; ntp < 8; ++ntp) {
                int row = ntp * 16 + (lane & 7) + ((lane >> 4) << 3);
                int col = ks * 16 + (((lane >> 3) & 1) << 3);
                u32 bh4[4], bl4[4];
                LDSM4(bh4[0], bh4[1], bh4[2], bh4[3], khb + (row * RS + col) * 2);
                LDSM4(bl4[0], bl4[1], bl4[2], bl4[3], klb + (row * RS + col) * 2);
                mma_bf16(S[2*ntp],   qh[ks], bh4[0], bh4[1]);
                mma_bf16(S[2*ntp],   qh[ks], bl4[0], bl4[1]);
                mma_bf16(S[2*ntp],   ql[ks], bh4[0], bh4[1]);
                mma_bf16(S[2*ntp+1], qh[ks], bh4[2], bh4[3]);
                mma_bf16(S[2*ntp+1], qh[ks], bl4[2], bl4[3]);
                mma_bf16(S[2*ntp+1], ql[ks], bh4[2], bh4[3]);
            }
        }

        // ---- online softmax ----
        float mx0 = NEGINF, mx1 = NEGINF;
        #pragma unroll
        for (int nt = 0; nt < 16; ++nt) {
            S[nt][0] = S[nt][0] * 0.125f + bias;
            S[nt][1] = S[nt][1] * 0.125f + bias;
            S[nt][2] = S[nt][2] * 0.125f + bias;
            S[nt][3] = S[nt][3] * 0.125f + bias;
            mx0 = fmaxf(mx0, fmaxf(S[nt][0], S[nt][1]));
            mx1 = fmaxf(mx1, fmaxf(S[nt][2], S[nt][3]));
        }
        mx0 = fmaxf(mx0, __shfl_xor_sync(0xffffffffu, mx0, 1));
        mx0 = fmaxf(mx0, __shfl_xor_sync(0xffffffffu, mx0, 2));
        mx1 = fmaxf(mx1, __shfl_xor_sync(0xffffffffu, mx1, 1));
        mx1 = fmaxf(mx1, __shfl_xor_sync(0xffffffffu, mx1, 2));
        float mn0 = fmaxf(m0r, mx0), mn1 = fmaxf(m1r, mx1);
        float f0 = __expf(m0r - mn0), f1 = __expf(m1r - mn1);
        m0r = mn0; m1r = mn1;
        #pragma unroll
        for (int nt = 0; nt < 8; ++nt) {
            O[nt][0] *= f0; O[nt][1] *= f0;
            O[nt][2] *= f1; O[nt][3] *= f1;
        }

        // ---- exp + fp16 pack + PV ----
        float s0 = 0.f, s1 = 0.f;
        #pragma unroll
        for (int j = 0; j < 8; ++j) {
            u32 aP[4];
            #pragma unroll
            for (int q = 0; q < 2; ++q) {
                int nt = 2 * j + q;
                float p0 = __expf(S[nt][0] - mn0), p1 = __expf(S[nt][1] - mn0);
                float p2 = __expf(S[nt][2] - mn1), p3 = __expf(S[nt][3] - mn1);
                s0 += p0 + p1; s1 += p2 + p3;
                aP[2*q]   = f16x2(p1, p0);
                aP[2*q+1] = f16x2(p3, p2);
            }
            #pragma unroll
            for (int v = 0; v < 4; ++v) {
                int row = j * 16 + (lane & 7) + (((lane >> 3) & 1) << 3);
                int col = v * 16 + ((lane >> 4) << 3);
                u32 bv4[4];
                LDSM4T(bv4[0], bv4[1], bv4[2], bv4[3], vhb + (row * RS + col) * 2);
                mma_f16(O[2*v],   aP, bv4[0], bv4[1]);
                mma_f16(O[2*v+1], aP, bv4[2], bv4[3]);
            }
        }
        s0 += __shfl_xor_sync(0xffffffffu, s0, 1);
        s0 += __shfl_xor_sync(0xffffffffu, s0, 2);
        s1 += __shfl_xor_sync(0xffffffffu, s1, 1);
        s1 += __shfl_xor_sync(0xffffffffu, s1, 2);
        l0r = l0r * f0 + s0;
        l1r = l1r * f1 + s1;
        __syncthreads();   // all reads of stage kb&1 done before issue(kb+2)
    }

    // ---- epilogue ----
    float i0 = 1.f / l0r, i1 = 1.f / l1r;
    int r0 = q0 + w * 16 + g;
    #pragma unroll
    for (int nt = 0; nt < 8; ++nt) {
        int cc = nt * 8 + c2 * 2;
        float2 v0 = make_float2(O[nt][0] * i0, O[nt][1] * i0);
        float2 v1 = make_float2(O[nt][2] * i1, O[nt][3] * i1);
        *(float2*)&out[base + (size_t)r0 * D_MODEL + cc] = v0;
        *(float2*)&out[base + (size_t)(r0 + 8) * D_MODEL + cc] = v1;
    }
}

// =========================================================================
extern "C" void kernel_launch(void* const* d_in, const int* in_sizes, int n_in,
                              void* d_out, int out_size)
{
    (void)in_sizes; (void)n_in; (void)out_size;
    const float* Xs   = (const float*)d_in[0];
    const float* Xt   = (const float*)d_in[1];
    const float* W_qs = (const float*)d_in[2];
    const float* b_qs = (const float*)d_in[3];
    const float* W_qt = (const float*)d_in[4];
    const float* b_qt = (const float*)d_in[5];
    const float* W_ks = (const float*)d_in[6];
    const float* b_ks = (const float*)d_in[7];
    const float* W_kt = (const float*)d_in[8];
    const float* b_kt = (const float*)d_in[9];
    const float* W_vs = (const float*)d_in[10];
    const float* b_vs = (const float*)d_in[11];
    const float* W_vt = (const float*)d_in[12];
    const float* b_vt = (const float*)d_in[13];
    const float* abias = (const float*)d_in[14];
    float* out = (float*)d_out;

    // 1) fp16 pre-convert of A and W
    conv_A_kernel<<<(M_TOT * (K_TOT / 8) + 255) / 256, 256>>>(Xs, Xt);
    conv_W_kernel<<<dim3((D_MODEL * (K_TOT / 8) + 255) / 256, 1, 3), 256>>>(
        W_qs, W_qt, W_ks, W_kt, W_vs, W_vt);

    // 2) tensor-core projections with fused split epilogue
    cudaFuncSetAttribute(proj_mma_kernel,
                         cudaFuncAttributeMaxDynamicSharedMemorySize, PSM_TOTAL);
    proj_mma_kernel<<<dim3(M_TOT / 128, D_MODEL / 256, 3), 256, PSM_TOTAL>>>(
        b_qs, b_qt, b_ks, b_kt, b_vs, b_vt);

    // 3) tensor-core attention (bf16x3 QK, fp16 PV, 2 CTAs/SM)
    cudaFuncSetAttribute(attn_mma_kernel,
                         cudaFuncAttributeMaxDynamicSharedMemorySize, ATT_SMEM);
    attn_mma_kernel<<<dim3(S_LEN / 64, NBATCH * NH), 128, ATT_SMEM>>>(
        out, abias);
}

// round 16
// speedup vs baseline: 1.0224x; 1.0224x over previous
#include <cuda_runtime.h>
#include <cuda_fp16.h>
#include <cstdint>

typedef unsigned long long u64;
typedef unsigned int u32;
typedef unsigned short u16;

#define D_MODEL 1024
#define S_LEN   2048
#define NBATCH  4
#define NH      16
#define DKH     64
#define M_TOT   (NBATCH * S_LEN)   /* 8192 */
#define K_TOT   2048               /* concat of Xs|Xt feature dims */

// Scratch (no allocs).
__device__ u16 g_Ah[(size_t)M_TOT * K_TOT];            // [Xs|Xt], fp16
__device__ u16 g_Wh[3][(size_t)D_MODEL * K_TOT];       // [W_zs|W_zt], fp16
__device__ u16 g_Qh[(size_t)M_TOT * D_MODEL];          // Q bf16 hi
__device__ u16 g_Ql[(size_t)M_TOT * D_MODEL];          // Q bf16 lo
__device__ u16 g_Kh[(size_t)M_TOT * D_MODEL];          // K bf16 hi
__device__ u16 g_Kl[(size_t)M_TOT * D_MODEL];          // K bf16 lo
__device__ u16 g_Vh[(size_t)M_TOT * D_MODEL];          // V fp16

// ---------------- baseline (sm_80+) primitives ----------------
__device__ __forceinline__ u32 smem_u32(const void* p) {
    u32 a; asm("{ .reg .u64 t; cvta.to.shared.u64 t, %1; cvt.u32.u64 %0, t; }"
               : "=r"(a) : "l"(p));
    return a;
}
__device__ __forceinline__ void cp16(u32 dst, const void* src) {
    asm volatile("cp.async.cg.shared.global [%0], [%1], 16;" :: "r"(dst), "l"(src));
}
__device__ __forceinline__ void cp_commit() {
    asm volatile("cp.async.commit_group;" ::: "memory");
}
template <int N> __device__ __forceinline__ void cp_wait() {
    asm volatile("cp.async.wait_group %0;" :: "n"(N) : "memory");
}
__device__ __forceinline__ float ex2(float x) {
    float r; asm("ex2.approx.f32 %0,%1;" : "=f"(r) : "f"(x)); return r;
}
// bf16: D = A(16x16,row) * B(16x8,col) + D
__device__ __forceinline__ void mma_bf16(float* c, const u32* a, u32 b0, u32 b1) {
    asm volatile(
        "mma.sync.aligned.m16n8k16.row.col.f32.bf16.bf16.f32 "
        "{%0,%1,%2,%3},{%4,%5,%6,%7},{%8,%9},{%0,%1,%2,%3};"
        : "+f"(c[0]), "+f"(c[1]), "+f"(c[2]), "+f"(c[3])
        : "r"(a[0]), "r"(a[1]), "r"(a[2]), "r"(a[3]), "r"(b0), "r"(b1));
}
// f16: D = A(16x16,row) * B(16x8,col) + D
__device__ __forceinline__ void mma_f16(float* c, const u32* a, u32 b0, u32 b1) {
    asm volatile(
        "mma.sync.aligned.m16n8k16.row.col.f32.f16.f16.f32 "
        "{%0,%1,%2,%3},{%4,%5,%6,%7},{%8,%9},{%0,%1,%2,%3};"
        : "+f"(c[0]), "+f"(c[1]), "+f"(c[2]), "+f"(c[3])
        : "r"(a[0]), "r"(a[1]), "r"(a[2]), "r"(a[3]), "r"(b0), "r"(b1));
}
#define LDSM4(r0, r1, r2, r3, a)                                             \
    asm volatile("ldmatrix.sync.aligned.m8n8.x4.shared.b16 {%0,%1,%2,%3},[%4];" \
        : "=r"(r0), "=r"(r1), "=r"(r2), "=r"(r3) : "r"(a))
#define LDSM4T(r0, r1, r2, r3, a)                                            \
    asm volatile("ldmatrix.sync.aligned.m8n8.x4.trans.shared.b16 {%0,%1,%2,%3},[%4];" \
        : "=r"(r0), "=r"(r1), "=r"(r2), "=r"(r3) : "r"(a))

// bf16 pack/unpack (hi goes to upper 16 bits)
__device__ __forceinline__ u32 bf16x2(float hi, float lo) {
    u32 d; asm("cvt.rn.bf16x2.f32 %0,%1,%2;" : "=r"(d) : "f"(hi), "f"(lo)); return d;
}
__device__ __forceinline__ float bflo(u32 x) { return __uint_as_float(x << 16); }
__device__ __forceinline__ float bfhi(u32 x) { return __uint_as_float(x & 0xffff0000u); }
// f16 pack (lo in low half, hi in high half), rne = unbiased
__device__ __forceinline__ u32 f16x2(float hi, float lo) {
    __half2 h = __floats2half2_rn(lo, hi);
    return *(u32*)&h;
}

// =========================================================================
// Pre-convert: fp16 A = [Xs|Xt] and W_z = [W_zs|W_zt].
// =========================================================================
__global__ __launch_bounds__(256) void conv_A_kernel(
    const float* __restrict__ Xs, const float* __restrict__ Xt)
{
    int idx = blockIdx.x * 256 + threadIdx.x;      // over 8192*256 chunks of 8
    if (idx >= M_TOT * (K_TOT / 8)) return;
    int row = idx >> 8, c8 = idx & 255;
    int col = c8 * 8;
    const float* src = (col < 1024) ? &Xs[(size_t)row * 1024 + col]
                                    : &Xt[(size_t)row * 1024 + col - 1024];
    float4 v0 = ((const float4*)src)[0];
    float4 v1 = ((const float4*)src)[1];
    uint4 o;
    o.x = f16x2(v0.y, v0.x); o.y = f16x2(v0.w, v0.z);
    o.z = f16x2(v1.y, v1.x); o.w = f16x2(v1.w, v1.z);
    *(uint4*)&g_Ah[(size_t)row * K_TOT + col] = o;
}

__global__ __launch_bounds__(256) void conv_W_kernel(
    const float* __restrict__ Wqs, const float* __restrict__ Wqt,
    const float* __restrict__ Wks, const float* __restrict__ Wkt,
    const float* __restrict__ Wvs, const float* __restrict__ Wvt)
{
    int z = blockIdx.z;
    const float *Wa, *Wb;
    if (z == 0)      { Wa = Wqs; Wb = Wqt; }
    else if (z == 1) { Wa = Wks; Wb = Wkt; }
    else             { Wa = Wvs; Wb = Wvt; }
    int idx = blockIdx.x * 256 + threadIdx.x;      // over 1024*256 chunks of 8
    if (idx >= D_MODEL * (K_TOT / 8)) return;
    int row = idx >> 8, c8 = idx & 255;
    int col = c8 * 8;
    const float* src = (col < 1024) ? &Wa[(size_t)row * 1024 + col]
                                    : &Wb[(size_t)row * 1024 + col - 1024];
    float4 v0 = ((const float4*)src)[0];
    float4 v1 = ((const float4*)src)[1];
    uint4 o;
    o.x = f16x2(v0.y, v0.x); o.y = f16x2(v0.w, v0.z);
    o.z = f16x2(v1.y, v1.x); o.w = f16x2(v1.w, v1.z);
    *(uint4*)&g_Wh[z][(size_t)row * K_TOT + col] = o;
}

// =========================================================================
// Projection GEMM via mma.sync f16 (fp32 accum), fused split epilogue.
// (unchanged R14 — passing, near its floor)
// =========================================================================
#define PJ_KC     64
#define PJ_NK     (K_TOT / PJ_KC)    /* 32 */
#define PRS       72                 /* u16 row stride (144B) */
#define PSTG_A    (128 * PRS * 2)    /* 18432 B */
#define PSTG_B    (256 * PRS * 2)    /* 36864 B */
#define PSTG      (PSTG_A + PSTG_B)  /* 55296 B */
#define PN_STG    4
#define PSM_BIAS  (PN_STG * PSTG)    /* 221184 */
#define PSM_TOTAL (PSM_BIAS + 1024 + 64)

__global__ void __launch_bounds__(256, 1) proj_mma_kernel(
    const float* __restrict__ bqs, const float* __restrict__ bqt,
    const float* __restrict__ bks, const float* __restrict__ bkt,
    const float* __restrict__ bvs, const float* __restrict__ bvt)
{
    extern __shared__ char sm[];
    const u32 smb = smem_u32(sm);
    const int t    = threadIdx.x;
    const int wid  = t >> 5;
    const int lane = t & 31;
    const int g    = lane >> 2;
    const int c    = lane & 3;
    const int wm   = (wid >> 2) * 64;
    const int wn   = (wid & 3) * 64;
    const int m0   = blockIdx.x * 128;
    const int n0   = blockIdx.y * 256;
    const int z    = blockIdx.z;

    const float* bA; const float* bB;
    if (z == 0)      { bA = bqs; bB = bqt; }
    else if (z == 1) { bA = bks; bB = bkt; }
    else             { bA = bvs; bB = bvt; }

    const u16* gAp = g_Ah;
    const u16* gWp = g_Wh[z];

    if (t < 64) {
        float4 a = *(const float4*)&bA[n0 + t * 4];
        float4 b = *(const float4*)&bB[n0 + t * 4];
        *(float4*)(sm + PSM_BIAS + t * 16) =
            make_float4(a.x + b.x, a.y + b.y, a.z + b.z, a.w + b.w);
    }

    float acc[4][8][4];
    #pragma unroll
    for (int mt = 0; mt < 4; ++mt)
        #pragma unroll
        for (int nt = 0; nt < 8; ++nt)
            #pragma unroll
            for (int j = 0; j < 4; ++j) acc[mt][nt][j] = 0.f;

    auto issue = [&](int i) {
        const int s  = i % PN_STG;
        const int kc = i * PJ_KC;
        const u32 abase = smb + s * PSTG;
        const u32 bbase = abase + PSTG_A;
        #pragma unroll
        for (int j = 0; j < 4; ++j) {              // A: 1024 x 16B
            int sid = t + j * 256;
            int row = sid >> 3, seg = sid & 7;
            cp16(abase + row * (PRS * 2) + seg * 16,
                 &gAp[(size_t)(m0 + row) * K_TOT + kc + seg * 8]);
        }
        #pragma unroll
        for (int j = 0; j < 8; ++j) {              // B: 2048 x 16B
            int sid = t + j * 256;
            int row = sid >> 3, seg = sid & 7;
            cp16(bbase + row * (PRS * 2) + seg * 16,
                 &gWp[(size_t)(n0 + row) * K_TOT + kc + seg * 8]);
        }
        cp_commit();
    };

    issue(0);
    issue(1);

    #pragma unroll 1
    for (int i = 0; i < PJ_NK; ++i) {
        if (i + 2 < PJ_NK)      { issue(i + 2); cp_wait<2>(); }
        else if (i + 1 < PJ_NK) { cp_wait<1>(); }
        else                    { cp_wait<0>(); }
        __syncthreads();    // single barrier (4-stage, distance-2 proof: R14)

        const int s = i % PN_STG;
        const u32 As = smb + s * PSTG;
        const u32 Bs = As + PSTG_A;

        #pragma unroll
        for (int ks = 0; ks < 4; ++ks) {
            u32 a[4][4], b[4][4];
            #pragma unroll
            for (int mt = 0; mt < 4; ++mt) {
                int row = wm + mt * 16 + (lane & 15);
                int col = ks * 16 + ((lane >> 4) << 3);
                LDSM4(a[mt][0], a[mt][1], a[mt][2], a[mt][3],
                      As + (row * PRS + col) * 2);
            }
            #pragma unroll
            for (int np = 0; np < 4; ++np) {
                int row = wn + np * 16 + (lane & 7) + ((lane >> 4) << 3);
                int col = ks * 16 + (((lane >> 3) & 1) << 3);
                LDSM4(b[np][0], b[np][1], b[np][2], b[np][3],
                      Bs + (row * PRS + col) * 2);
            }
            #pragma unroll
            for (int mt = 0; mt < 4; ++mt)
                #pragma unroll
                for (int np = 0; np < 4; ++np) {
                    mma_f16(acc[mt][2*np],   a[mt], b[np][0], b[np][1]);
                    mma_f16(acc[mt][2*np+1], a[mt], b[np][2], b[np][3]);
                }
        }
    }

    // ---- fused epilogue: +bias, split-convert, store 16-bit ----
    const float* bias = (const float*)(sm + PSM_BIAS);
    #pragma unroll
    for (int mt = 0; mt < 4; ++mt) {
        #pragma unroll
        for (int nt = 0; nt < 8; ++nt) {
            int cc = wn + nt * 8 + 2 * c;
            int r0 = m0 + wm + mt * 16 + g;
            float b0 = bias[cc], b1 = bias[cc + 1];
            float x0 = acc[mt][nt][0] + b0, x1 = acc[mt][nt][1] + b1;
            float y0 = acc[mt][nt][2] + b0, y1 = acc[mt][nt][3] + b1;
            size_t o0 = (size_t)r0 * D_MODEL + n0 + cc;
            size_t o1 = (size_t)(r0 + 8) * D_MODEL + n0 + cc;
            if (z == 2) {
                *(u32*)&g_Vh[o0] = f16x2(x1, x0);
                *(u32*)&g_Vh[o1] = f16x2(y1, y0);
            } else {
                u32 h0 = bf16x2(x1, x0);
                u32 h1 = bf16x2(y1, y0);
                u32 l0 = bf16x2(x1 - bfhi(h0), x0 - bflo(h0));
                u32 l1 = bf16x2(y1 - bfhi(h1), y0 - bflo(h1));
                u16* dh = (z == 0) ? g_Qh : g_Kh;
                u16* dl = (z == 0) ? g_Ql : g_Kl;
                *(u32*)&dh[o0] = h0;  *(u32*)&dh[o1] = h1;
                *(u32*)&dl[o0] = l0;  *(u32*)&dl[o1] = l1;
            }
        }
    }
}

// =========================================================================
// Flash attention on tensor cores.  R16: R14 shape (256 thr, 128 q-rows,
// 3-stage, single sync) + sub-block softmax overlap:
//   QK(s0); QK(s1); softmax(s0); PV(s0); softmax(s1); PV(s1)
// so softmax ALU/MUFU overlaps in-flight HMMA.  exp in exp2 domain.
// =========================================================================
#define RS       72                    /* u16 row stride (144B) */
#define TILE_B   (128 * RS * 2)        /* 18432 B */
#define STG3     (3 * TILE_B)          /* Kh+Kl+Vh = 55296 B */
#define AT_NSTG  3
#define ATT_SMEM (AT_NSTG * STG3)      /* 165888 B */
#define NT       (S_LEN / 128)         /* 16 */
#define LOG2E    1.4426950408889634f

__global__ void __launch_bounds__(256, 1) attn_mma_kernel(
    float* __restrict__ out, const float* __restrict__ biasp)
{
    extern __shared__ char smc[];
    const u32 smb = smem_u32(smc);

    const int t = threadIdx.x, w = t >> 5, lane = t & 31;
    const int g = lane >> 2, c2 = lane & 3;
    const int q0 = blockIdx.x * 128;
    const int bh = blockIdx.y, b = bh >> 4, h = bh & 15;
    const size_t base  = (size_t)b * S_LEN * D_MODEL + (size_t)h * DKH;
    const size_t rowb  = (size_t)b * S_LEN;
    const int    colb  = h * DKH;
    const float biasl = biasp[0] * LOG2E;       // bias in exp2 domain
    const float SC    = 0.125f * LOG2E;         // scale in exp2 domain
    const float NEGINF = __int_as_float(0xff800000);

    // cp.async pre-split K/V tile i -> stage i%3
    auto stage_issue = [&](int i) {
        const u32 sb = smb + (i % AT_NSTG) * STG3;
        const size_t r0 = (rowb + (size_t)i * 128) * D_MODEL + colb;
        #pragma unroll
        for (int j = 0; j < 4; ++j) {
            int sid = t + j * 256;
            int row = sid >> 3, seg = sid & 7;
            size_t src = r0 + (size_t)row * D_MODEL + seg * 8;
            u32 dst = sb + row * (RS * 2) + seg * 16;
            cp16(dst,              &g_Kh[src]);
            cp16(dst + TILE_B,     &g_Kl[src]);
            cp16(dst + 2 * TILE_B, &g_Vh[src]);
        }
        cp_commit();
    };

    stage_issue(0);

    // Q tiles (pre-split) staged through stage-2 area, then into registers.
    {
        const u32 sb = smb + 2 * STG3;
        const size_t r0 = (rowb + (size_t)q0) * D_MODEL + colb;
        #pragma unroll
        for (int j = 0; j < 4; ++j) {
            int sid = t + j * 256;
            int row = sid >> 3, seg = sid & 7;
            size_t src = r0 + (size_t)row * D_MODEL + seg * 8;
            u32 dst = sb + row * (RS * 2) + seg * 16;
            cp16(dst,          &g_Qh[src]);
            cp16(dst + TILE_B, &g_Ql[src]);
        }
        cp_commit();
    }
    cp_wait<0>();
    __syncthreads();

    u32 qh[4][4], ql[4][4];
    {
        int row = w * 16 + (lane & 15);
        int cb  = (lane >> 4) << 3;
        #pragma unroll
        for (int ks = 0; ks < 4; ++ks) {
            u32 ah = smb + 2 * STG3 + (row * RS + ks * 16 + cb) * 2;
            LDSM4(qh[ks][0], qh[ks][1], qh[ks][2], qh[ks][3], ah);
            LDSM4(ql[ks][0], ql[ks][1], ql[ks][2], ql[ks][3], ah + TILE_B);
        }
    }
    // stage-2 overwrite first happens at issue(2) after sync(0): safe (R14 proof)

    float m0r = NEGINF, m1r = NEGINF, l0r = 0.f, l1r = 0.f;
    float O[8][4];
    #pragma unroll
    for (int nt = 0; nt < 8; ++nt)
        #pragma unroll
        for (int j = 0; j < 4; ++j) O[nt][j] = 0.f;

    #pragma unroll 1
    for (int kb = 0; kb < NT; ++kb) {
        if (kb + 1 < NT) { stage_issue(kb + 1); cp_wait<1>(); }
        else             { cp_wait<0>(); }
        __syncthreads();   // single barrier per tile (3-stage proof: R14)

        const u32 sb  = smb + (kb % AT_NSTG) * STG3;
        const u32 khb = sb, klb = sb + TILE_B, vhb = sb + 2 * TILE_B;

        // ---- S = Q K^T : bf16x3, sub-block s0 (k-rows 0..63) then s1 ----
        float S[16][4];
        #pragma unroll
        for (int nt = 0; nt < 16; ++nt)
            #pragma unroll
            for (int j = 0; j < 4; ++j) S[nt][j] = 0.f;

        #pragma unroll
        for (int half = 0; half < 2; ++half) {
            #pragma unroll
            for (int ks = 0; ks < 4; ++ks) {
                #pragma unroll
                for (int np = 0; np < 4; ++np) {
                    int ntp = half * 4 + np;
                    int row = ntp * 16 + (lane & 7) + ((lane >> 4) << 3);
                    int col = ks * 16 + (((lane >> 3) & 1) << 3);
                    u32 bh4[4], bl4[4];
                    LDSM4(bh4[0], bh4[1], bh4[2], bh4[3], khb + (row * RS + col) * 2);
                    LDSM4(bl4[0], bl4[1], bl4[2], bl4[3], klb + (row * RS + col) * 2);
                    mma_bf16(S[2*ntp],   qh[ks], bh4[0], bh4[1]);
                    mma_bf16(S[2*ntp],   qh[ks], bl4[0], bl4[1]);
                    mma_bf16(S[2*ntp],   ql[ks], bh4[0], bh4[1]);
                    mma_bf16(S[2*ntp+1], qh[ks], bh4[2], bh4[3]);
                    mma_bf16(S[2*ntp+1], qh[ks], bl4[2], bl4[3]);
                    mma_bf16(S[2*ntp+1], ql[ks], bh4[2], bh4[3]);
                }
            }
        }

        // ---- per-sub-block online softmax + PV.  softmax(s0) overlaps the
        //      in-flight tail of QK(s1); softmax(s1) overlaps PV(s0). ----
        #pragma unroll
        for (int sbk = 0; sbk < 2; ++sbk) {
            float mx0 = NEGINF, mx1 = NEGINF;
            #pragma unroll
            for (int q = 0; q < 8; ++q) {
                int nt = sbk * 8 + q;
                S[nt][0] = S[nt][0] * SC + biasl;
                S[nt][1] = S[nt][1] * SC + biasl;
                S[nt][2] = S[nt][2] * SC + biasl;
                S[nt][3] = S[nt][3] * SC + biasl;
                mx0 = fmaxf(mx0, fmaxf(S[nt][0], S[nt][1]));
                mx1 = fmaxf(mx1, fmaxf(S[nt][2], S[nt][3]));
            }
            mx0 = fmaxf(mx0, __shfl_xor_sync(0xffffffffu, mx0, 1));
            mx0 = fmaxf(mx0, __shfl_xor_sync(0xffffffffu, mx0, 2));
            mx1 = fmaxf(mx1, __shfl_xor_sync(0xffffffffu, mx1, 1));
            mx1 = fmaxf(mx1, __shfl_xor_sync(0xffffffffu, mx1, 2));
            float mn0 = fmaxf(m0r, mx0), mn1 = fmaxf(m1r, mx1);
            float f0 = ex2(m0r - mn0), f1 = ex2(m1r - mn1);
            m0r = mn0; m1r = mn1;
            #pragma unroll
            for (int nt = 0; nt < 8; ++nt) {
                O[nt][0] *= f0; O[nt][1] *= f0;
                O[nt][2] *= f1; O[nt][3] *= f1;
            }

            float sa = 0.f, sb2 = 0.f;
            #pragma unroll
            for (int jj = 0; jj < 4; ++jj) {
                int j = sbk * 4 + jj;
                u32 aP[4];
                #pragma unroll
                for (int q = 0; q < 2; ++q) {
                    int nt = 2 * j + q;
                    float p0 = ex2(S[nt][0] - mn0), p1 = ex2(S[nt][1] - mn0);
                    float p2 = ex2(S[nt][2] - mn1), p3 = ex2(S[nt][3] - mn1);
                    sa  += p0 + p1; sb2 += p2 + p3;
                    aP[2*q]   = f16x2(p1, p0);
                    aP[2*q+1] = f16x2(p3, p2);
                }
                #pragma unroll
                for (int v = 0; v < 4; ++v) {
                    int row = j * 16 + (lane & 7) + (((lane >> 3) & 1) << 3);
                    int col = v * 16 + ((lane >> 4) << 3);
                    u32 bv4[4];
                    LDSM4T(bv4[0], bv4[1], bv4[2], bv4[3], vhb + (row * RS + col) * 2);
                    mma_f16(O[2*v],   aP, bv4[0], bv4[1]);
                    mma_f16(O[2*v+1], aP, bv4[2], bv4[3]);
                }
            }
            sa  += __shfl_xor_sync(0xffffffffu, sa, 1);
            sa  += __shfl_xor_sync(0xffffffffu, sa, 2);
            sb2 += __shfl_xor_sync(0xffffffffu, sb2, 1);
            sb2 += __shfl_xor_sync(0xffffffffu, sb2, 2);
            l0r = l0r * f0 + sa;
            l1r = l1r * f1 + sb2;
        }
    }

    // ---- epilogue ----
    float i0 = 1.f / l0r, i1 = 1.f / l1r;
    int r0 = q0 + w * 16 + g;
    #pragma unroll
    for (int nt = 0; nt < 8; ++nt) {
        int cc = nt * 8 + c2 * 2;
        float2 v0 = make_float2(O[nt][0] * i0, O[nt][1] * i0);
        float2 v1 = make_float2(O[nt][2] * i1, O[nt][3] * i1);
        *(float2*)&out[base + (size_t)r0 * D_MODEL + cc] = v0;
        *(float2*)&out[base + (size_t)(r0 + 8) * D_MODEL + cc] = v1;
    }
}

// =========================================================================
extern "C" void kernel_launch(void* const* d_in, const int* in_sizes, int n_in,
                              void* d_out, int out_size)
{
    (void)in_sizes; (void)n_in; (void)out_size;
    const float* Xs   = (const float*)d_in[0];
    const float* Xt   = (const float*)d_in[1];
    const float* W_qs = (const float*)d_in[2];
    const float* b_qs = (const float*)d_in[3];
    const float* W_qt = (const float*)d_in[4];
    const float* b_qt = (const float*)d_in[5];
    const float* W_ks = (const float*)d_in[6];
    const float* b_ks = (const float*)d_in[7];
    const float* W_kt = (const float*)d_in[8];
    const float* b_kt = (const float*)d_in[9];
    const float* W_vs = (const float*)d_in[10];
    const float* b_vs = (const float*)d_in[11];
    const float* W_vt = (const float*)d_in[12];
    const float* b_vt = (const float*)d_in[13];
    const float* abias = (const float*)d_in[14];
    float* out = (float*)d_out;

    // 1) fp16 pre-convert of A and W
    conv_A_kernel<<<(M_TOT * (K_TOT / 8) + 255) / 256, 256>>>(Xs, Xt);
    conv_W_kernel<<<dim3((D_MODEL * (K_TOT / 8) + 255) / 256, 1, 3), 256>>>(
        W_qs, W_qt, W_ks, W_kt, W_vs, W_vt);

    // 2) tensor-core projections with fused split epilogue
    cudaFuncSetAttribute(proj_mma_kernel,
                         cudaFuncAttributeMaxDynamicSharedMemorySize, PSM_TOTAL);
    proj_mma_kernel<<<dim3(M_TOT / 128, D_MODEL / 256, 3), 256, PSM_TOTAL>>>(
        b_qs, b_qt, b_ks, b_kt, b_vs, b_vt);

    // 3) tensor-core attention (bf16x3 QK, fp16 PV, sub-block overlap)
    cudaFuncSetAttribute(attn_mma_kernel,
                         cudaFuncAttributeMaxDynamicSharedMemorySize, ATT_SMEM);
    attn_mma_kernel<<<dim3(S_LEN / 128, NBATCH * NH), 256, ATT_SMEM>>>(
        out, abias);
}